// round 3
// baseline (speedup 1.0000x reference)
#include <cuda_runtime.h>
#include <cuda_fp16.h>
#include <cstdint>

#define DD 64
#define HH 128
#define CIN 32
#define COUT 64

// sign tensor: [(d*128+h)][w'=0..129][c=0..31] fp16, w'=0 and 129 are zero pad
__device__ __align__(16) __half g_sign[(size_t)DD * HH * 130 * CIN];
// repacked weights: [o][k], k = (kd*9+kh*3+kw)*32 + c
__device__ __align__(16) __half g_wT[COUT * 864];

// ---------------- conv kernel SMEM layout ----------------
#define SROW_BYTES 80            // 32 halfs (64B) + 16B pad
#define TILE_BYTES 10400         // 130 rows * 80B
#define W_OFF      93600         // 9 * TILE_BYTES
#define WROW_BYTES 1744          // 864 halfs (1728B) + 16B pad
#define BIAS_OFF   205216        // W_OFF + 64*WROW_BYTES
#define SMEM_TOTAL 205472
// epilogue overlays [0, 33792) as float stage[64][132]

// ---------------------------------------------------------------------------
// Kernel 1: binarize + transpose x -> [d][h][w'][c] fp16 with w halo baked in
// ---------------------------------------------------------------------------
__global__ __launch_bounds__(256) void sign_kernel(const float* __restrict__ x) {
    __shared__ __align__(16) __half tr[128 * 40];   // [w][c], rows padded to 80B
    const int dh = blockIdx.x;                      // d*128 + h
    const int d = dh >> 7, h = dh & 127;
    const float* xp = x + (size_t)d * 16384 + (size_t)h * 128;

    for (int i = threadIdx.x; i < 4096; i += 256) {
        const int c = i >> 7, w = i & 127;
        const float v = xp[(size_t)c * 1048576 + w];
        const float s = (v > 0.f) ? 1.f : ((v < 0.f) ? -1.f : 0.f);
        tr[w * 40 + c] = __float2half_rn(s);
    }
    __syncthreads();

    __half* dst = g_sign + (size_t)dh * (130 * 32);
    for (int i = threadIdx.x; i < 520; i += 256) {
        const int wp = i >> 2, part = i & 3;
        uint4 v;
        if (wp == 0 || wp == 129) { v.x = v.y = v.z = v.w = 0u; }
        else v = *reinterpret_cast<const uint4*>(&tr[(wp - 1) * 40 + part * 8]);
        *reinterpret_cast<uint4*>(&dst[wp * 32 + part * 8]) = v;
    }
}

// ---------------------------------------------------------------------------
// Kernel 2: repack weights OIDHW -> [o][off*32 + c] fp16
// ---------------------------------------------------------------------------
__global__ __launch_bounds__(256) void wprep_kernel(const float* __restrict__ Wf) {
    const int i = blockIdx.x * 256 + threadIdx.x;
    if (i < COUT * 864) {
        const int o = i / 864, r = i % 864;
        const int off = r >> 5, c = r & 31;          // off = kd*9+kh*3+kw
        g_wT[i] = __float2half_rn(Wf[o * 864 + c * 27 + off]);
    }
}

// ---------------------------------------------------------------------------
// mma helpers
// ---------------------------------------------------------------------------
__device__ __forceinline__ void ldmx4(uint32_t& r0, uint32_t& r1, uint32_t& r2,
                                      uint32_t& r3, uint32_t addr) {
    asm volatile("ldmatrix.sync.aligned.m8n8.x4.shared.b16 {%0,%1,%2,%3}, [%4];"
                 : "=r"(r0), "=r"(r1), "=r"(r2), "=r"(r3) : "r"(addr));
}
__device__ __forceinline__ void mma16816(float c[4], const uint32_t a[4],
                                         uint32_t b0, uint32_t b1) {
    asm volatile(
        "mma.sync.aligned.m16n8k16.row.col.f32.f16.f16.f32 "
        "{%0,%1,%2,%3}, {%4,%5,%6,%7}, {%8,%9}, {%0,%1,%2,%3};"
        : "+f"(c[0]), "+f"(c[1]), "+f"(c[2]), "+f"(c[3])
        : "r"(a[0]), "r"(a[1]), "r"(a[2]), "r"(a[3]), "r"(b0), "r"(b1));
}

// load all operand fragments for one k-step (off = ks>>1, chunk = ks&1)
__device__ __forceinline__ void load_kstep(uint32_t smemB, uint32_t aLane,
                                           uint32_t bLane, int mb, int ks,
                                           uint32_t aF[2][4], uint32_t bF[4][2]) {
    const int off = ks >> 1, chunk = ks & 1;
    const int kd = off / 9;
    const int rr = off - kd * 9;
    const int kh = rr / 3;
    const int kw = rr - kh * 3;
    const int t = kd * 3 + kh;
    // A: rows = w + kw within tile t
    const uint32_t abase = smemB + t * TILE_BYTES + (mb + kw) * SROW_BYTES
                         + chunk * 32 + aLane;
    ldmx4(aF[0][0], aF[0][1], aF[0][2], aF[0][3], abase);
    ldmx4(aF[1][0], aF[1][1], aF[1][2], aF[1][3], abase + 16 * SROW_BYTES);
    // B: weight rows, k byte offset = off*64 + chunk*32
    const uint32_t bbase = smemB + bLane + off * 64 + chunk * 32;
    ldmx4(bF[0][0], bF[0][1], bF[1][0], bF[1][1], bbase);                   // n 0-15
    ldmx4(bF[2][0], bF[2][1], bF[3][0], bF[3][1], bbase + 16 * WROW_BYTES); // n 16-31
}

// ---------------------------------------------------------------------------
// Kernel 3: one CTA per (d,h). Output tile [w=128][o=64]; 8 warps m32 x n32.
// ---------------------------------------------------------------------------
__global__ __launch_bounds__(256, 1) void conv_kernel(const float* __restrict__ bias,
                                                      float* __restrict__ out) {
    extern __shared__ __align__(16) char smem[];
    const int tid = threadIdx.x;
    const int dh = blockIdx.x;
    const int d = dh >> 7, h = dh & 127;

    if (tid < 64)
        *reinterpret_cast<float*>(smem + BIAS_OFF + tid * 4) = bias[tid];

    // weights: 64 rows of 864 halfs -> 1744B padded rows
    for (int i = tid; i < 6912; i += 256) {
        const int o = i / 108, jj = i % 108;
        const uint4 v = *reinterpret_cast<const uint4*>(&g_wT[o * 864 + jj * 8]);
        *reinterpret_cast<uint4*>(smem + W_OFF + o * WROW_BYTES + jj * 16) = v;
    }

    // 9 halo sign tiles (zero-fill OOB d/h)
    for (int t = 0; t < 9; ++t) {
        const int dp = d + t / 3 - 1;
        const int hp = h + t % 3 - 1;
        char* dstT = smem + t * TILE_BYTES;
        if ((dp >= 0) & (dp < DD) & (hp >= 0) & (hp < HH)) {
            const __half* src = g_sign + (size_t)(dp * 128 + hp) * (130 * 32);
            for (int i = tid; i < 520; i += 256) {
                const int wp = i >> 2, part = i & 3;
                const uint4 v = *reinterpret_cast<const uint4*>(&src[wp * 32 + part * 8]);
                *reinterpret_cast<uint4*>(dstT + wp * SROW_BYTES + part * 16) = v;
            }
        } else {
            const uint4 z = {0u, 0u, 0u, 0u};
            for (int i = tid; i < 520; i += 256) {
                const int wp = i >> 2, part = i & 3;
                *reinterpret_cast<uint4*>(dstT + wp * SROW_BYTES + part * 16) = z;
            }
        }
    }
    __syncthreads();

    // ---- mainloop ----
    const int lane = tid & 31;
    const int warp = tid >> 5;
    const int mb = (warp >> 1) * 32;   // w base: 0,32,64,96
    const int nb = (warp & 1) * 32;    // o base: 0,32

    const uint32_t smemB = (uint32_t)__cvta_generic_to_shared(smem);
    // A lane offset: rows (lane&15), k-half (lane>>4)*16B
    const uint32_t aLane = (uint32_t)((lane & 15) * SROW_BYTES + (lane >> 4) * 16);
    // B lane offset: n rows (lane&7) + ((lane>>4)&1)*8 (+nb), k-half ((lane>>3)&1)*16B
    const uint32_t bLane = (uint32_t)(W_OFF
        + (nb + (lane & 7) + ((lane >> 4) & 1) * 8) * WROW_BYTES
        + ((lane >> 3) & 1) * 16);

    float acc[2][4][4];
    #pragma unroll
    for (int mf = 0; mf < 2; ++mf)
        #pragma unroll
        for (int nf = 0; nf < 4; ++nf)
            #pragma unroll
            for (int k = 0; k < 4; ++k) acc[mf][nf][k] = 0.f;

    uint32_t aF[2][2][4], bF[2][4][2];
    load_kstep(smemB, aLane, bLane, mb, 0, aF[0], bF[0]);

    #pragma unroll 2
    for (int ks = 0; ks < 54; ++ks) {
        const int cur = ks & 1, nxt = cur ^ 1;
        if (ks < 53)
            load_kstep(smemB, aLane, bLane, mb, ks + 1, aF[nxt], bF[nxt]);
        #pragma unroll
        for (int mf = 0; mf < 2; ++mf)
            #pragma unroll
            for (int nf = 0; nf < 4; ++nf)
                mma16816(acc[mf][nf], aF[cur][mf], bF[cur][nf][0], bF[cur][nf][1]);
    }
    __syncthreads();   // done reading tiles; reuse SMEM for staging

    // ---- epilogue: stage [o][w] (132-float padded rows), then coalesced store
    float* stage = reinterpret_cast<float*>(smem);
    const int g = lane >> 2;           // row-in-frag
    const int tt = lane & 3;           // col pair
    #pragma unroll
    for (int mf = 0; mf < 2; ++mf) {
        #pragma unroll
        for (int nf = 0; nf < 4; ++nf) {
            const int o = nb + nf * 8 + 2 * tt;
            const int w0 = mb + mf * 16 + g;
            stage[o * 132 + w0]             = acc[mf][nf][0];
            stage[(o + 1) * 132 + w0]       = acc[mf][nf][1];
            stage[o * 132 + w0 + 8]         = acc[mf][nf][2];
            stage[(o + 1) * 132 + w0 + 8]   = acc[mf][nf][3];
        }
    }
    __syncthreads();

    const float* biasS = reinterpret_cast<const float*>(smem + BIAS_OFF);
    float* outp = out + (size_t)dh * 128;
    #pragma unroll
    for (int it = 0; it < 8; ++it) {
        const int idx = it * 256 + tid;
        const int o = idx >> 5, w4 = (idx & 31) * 4;
        float4 v = *reinterpret_cast<const float4*>(&stage[o * 132 + w4]);
        const float bv = biasS[o];
        v.x += bv; v.y += bv; v.z += bv; v.w += bv;
        *reinterpret_cast<float4*>(&outp[(size_t)o * 1048576 + w4]) = v;
    }
}

extern "C" void kernel_launch(void* const* d_in, const int* in_sizes, int n_in,
                              void* d_out, int out_size) {
    const float* x  = (const float*)d_in[0];
    const float* Wf = (const float*)d_in[1];
    const float* b  = (const float*)d_in[2];
    float* out = (float*)d_out;

    static bool attr_done = false;
    if (!attr_done) {
        cudaFuncSetAttribute(conv_kernel,
                             cudaFuncAttributeMaxDynamicSharedMemorySize, SMEM_TOTAL);
        attr_done = true;
    }

    sign_kernel<<<DD * HH, 256>>>(x);
    wprep_kernel<<<(COUT * 864 + 255) / 256, 256>>>(Wf);
    conv_kernel<<<DD * HH, 256, SMEM_TOTAL>>>(b, out);
}

// round 6
// speedup vs baseline: 1.7462x; 1.7462x over previous
#include <cuda_runtime.h>
#include <cuda_fp16.h>
#include <cstdint>

#define DD 64
#define HH 128

// sign tensor: [(d*128+h)][w'=0..129][c=0..31] fp16, w'=0,129 zero pad (64B rows)
__device__ __align__(16) __half g_sign[(size_t)DD * HH * 130 * 32];
// repacked weights: [o][k], k = (kd*9+kh*3+kw)*32 + c
__device__ __align__(16) __half g_wT[64 * 864];

// ---------------- conv SMEM layout ----------------
#define SROW_BYTES 80            // 32 halfs (64B) + 16B pad (conflict-free ldmatrix)
#define TILE_B     10400         // 130 rows * 80B
#define W_OFF      93600         // 9 * TILE_B
#define WROW_BYTES 1744          // 864 halfs + 16B pad
#define BIAS_OFF   205216
#define SMEM_TOTAL 205472
#define RPC        8             // h rows per CTA

// ---------------------------------------------------------------------------
// Kernel 1: binarize + transpose x -> [d][h][w'][c] fp16, w halo baked in
// ---------------------------------------------------------------------------
__global__ __launch_bounds__(256) void sign_kernel(const float* __restrict__ x) {
    __shared__ __align__(16) __half tr[128 * 40];
    const int dh = blockIdx.x;
    const int d = dh >> 7, h = dh & 127;
    const float* xp = x + (size_t)d * 16384 + (size_t)h * 128;

    for (int i = threadIdx.x; i < 4096; i += 256) {
        const int c = i >> 7, w = i & 127;
        const float v = xp[(size_t)c * 1048576 + w];
        const float s = (v > 0.f) ? 1.f : ((v < 0.f) ? -1.f : 0.f);
        tr[w * 40 + c] = __float2half_rn(s);
    }
    __syncthreads();

    __half* dst = g_sign + (size_t)dh * (130 * 32);
    for (int i = threadIdx.x; i < 520; i += 256) {
        const int wp = i >> 2, part = i & 3;
        uint4 v;
        if (wp == 0 || wp == 129) { v.x = v.y = v.z = v.w = 0u; }
        else v = *reinterpret_cast<const uint4*>(&tr[(wp - 1) * 40 + part * 8]);
        *reinterpret_cast<uint4*>(&dst[wp * 32 + part * 8]) = v;
    }
}

// ---------------------------------------------------------------------------
// Kernel 2: repack weights OIDHW -> [o][off*32 + c] fp16
// ---------------------------------------------------------------------------
__global__ __launch_bounds__(256) void wprep_kernel(const float* __restrict__ Wf) {
    const int i = blockIdx.x * 256 + threadIdx.x;
    if (i < 64 * 864) {
        const int o = i / 864, r = i % 864;
        const int off = r >> 5, c = r & 31;
        g_wT[i] = __float2half_rn(Wf[o * 864 + c * 27 + off]);
    }
}

// ---------------------------------------------------------------------------
// mma / cp.async helpers
// ---------------------------------------------------------------------------
__device__ __forceinline__ void ldmx4(uint32_t& r0, uint32_t& r1, uint32_t& r2,
                                      uint32_t& r3, uint32_t addr) {
    asm volatile("ldmatrix.sync.aligned.m8n8.x4.shared.b16 {%0,%1,%2,%3}, [%4];"
                 : "=r"(r0), "=r"(r1), "=r"(r2), "=r"(r3) : "r"(addr));
}
__device__ __forceinline__ void mma16816(float c[4], const uint32_t a[4],
                                         uint32_t b0, uint32_t b1) {
    asm volatile(
        "mma.sync.aligned.m16n8k16.row.col.f32.f16.f16.f32 "
        "{%0,%1,%2,%3}, {%4,%5,%6,%7}, {%8,%9}, {%0,%1,%2,%3};"
        : "+f"(c[0]), "+f"(c[1]), "+f"(c[2]), "+f"(c[3])
        : "r"(a[0]), "r"(a[1]), "r"(a[2]), "r"(a[3]), "r"(b0), "r"(b1));
}
__device__ __forceinline__ void cp16(uint32_t dst, const void* src, uint32_t bytes) {
    asm volatile("cp.async.cg.shared.global [%0], [%1], 16, %2;"
                 :: "r"(dst), "l"(src), "r"(bytes) : "memory");
}
#define CP_COMMIT() asm volatile("cp.async.commit_group;" ::: "memory")
#define CP_WAIT0()  asm volatile("cp.async.wait_group 0;" ::: "memory")

// fragment load for one k-step: section s (=kh), j in [0,18)
__device__ __forceinline__ void load_ks(uint32_t smemB, uint32_t aLane,
                                        uint32_t bLane, int mb, int h, int s, int j,
                                        uint32_t aF[2][4], uint32_t bF[4][2]) {
    const int kd = j / 6, r = j % 6, kw = r >> 1, chunk = r & 1;
    const int off = kd * 9 + s * 3 + kw;
    const int hp = h + s - 1;
    const int slot = kd * 3 + ((hp + 3) % 3);
    const uint32_t abase = smemB + slot * TILE_B + (mb + kw) * SROW_BYTES
                         + chunk * 32 + aLane;
    ldmx4(aF[0][0], aF[0][1], aF[0][2], aF[0][3], abase);
    ldmx4(aF[1][0], aF[1][1], aF[1][2], aF[1][3], abase + 16 * SROW_BYTES);
    const uint32_t bbase = smemB + bLane + off * 64 + chunk * 32;
    ldmx4(bF[0][0], bF[0][1], bF[1][0], bF[1][1], bbase);
    ldmx4(bF[2][0], bF[2][1], bF[3][0], bF[3][1], bbase + 16 * WROW_BYTES);
}

// ---------------------------------------------------------------------------
// Kernel 3: persistent conv. One CTA per (d, 8-row h strip).
// ---------------------------------------------------------------------------
__global__ __launch_bounds__(256, 1) void conv_p(const float* __restrict__ bias,
                                                 float* __restrict__ out) {
    extern __shared__ __align__(16) char smem[];
    const int tid = threadIdx.x;
    const int d = blockIdx.x >> 4;
    const int h0 = (blockIdx.x & 15) * RPC;

    // ---- weights (once per CTA) ----
    for (int i = tid; i < 6912; i += 256) {
        const int o = i / 108, jj = i % 108;
        const uint4 v = *reinterpret_cast<const uint4*>(&g_wT[o * 864 + jj * 8]);
        *reinterpret_cast<uint4*>(smem + W_OFF + o * WROW_BYTES + jj * 16) = v;
    }

    // ---- preload 9 tiles: hp in {h0-1,h0,h0+1} x kd ----
    for (int t = 0; t < 9; ++t) {
        const int kd = t / 3, jj = t % 3;
        const int dp = d + kd - 1, hp = h0 - 1 + jj;
        char* dstT = smem + (kd * 3 + ((hp + 3) % 3)) * TILE_B;
        if (dp >= 0 && dp < 64 && hp >= 0 && hp < 128) {
            const char* src = (const char*)(g_sign + (size_t)(dp * 128 + hp) * 4160);
            for (int q = tid; q < 520; q += 256) {
                const int wp = q >> 2, part = q & 3;
                *reinterpret_cast<uint4*>(dstT + wp * SROW_BYTES + part * 16) =
                    *reinterpret_cast<const uint4*>(src + wp * 64 + part * 16);
            }
        } else {
            const uint4 z = {0u, 0u, 0u, 0u};
            for (int q = tid; q < 520; q += 256) {
                const int wp = q >> 2, part = q & 3;
                *reinterpret_cast<uint4*>(dstT + wp * SROW_BYTES + part * 16) = z;
            }
        }
    }

    const int lane = tid & 31;
    const int warp = tid >> 5;
    const int mb = (warp >> 1) * 32;   // w base: 0,32,64,96
    const int nb = (warp & 1) * 32;    // o base: 0,32
    const int g = lane >> 2, tt = lane & 3;

    // bias in registers
    float bReg[4][2];
    #pragma unroll
    for (int nf = 0; nf < 4; ++nf) {
        bReg[nf][0] = bias[nb + nf * 8 + 2 * tt];
        bReg[nf][1] = bias[nb + nf * 8 + 2 * tt + 1];
    }

    const uint32_t smemB = (uint32_t)__cvta_generic_to_shared(smem);
    const uint32_t aLane = (uint32_t)((lane & 15) * SROW_BYTES + (lane >> 4) * 16);
    const uint32_t bLane = (uint32_t)(W_OFF
        + (nb + (lane & 7) + ((lane >> 4) & 1) * 8) * WROW_BYTES
        + ((lane >> 3) & 1) * 16);

    __syncthreads();

    for (int i = 0; i < RPC; ++i) {
        const int h = h0 + i;

        float acc[2][4][4];
        #pragma unroll
        for (int mf = 0; mf < 2; ++mf)
            #pragma unroll
            for (int nf = 0; nf < 4; ++nf)
                #pragma unroll
                for (int k = 0; k < 4; ++k) acc[mf][nf][k] = 0.f;

        uint32_t aF[2][2][4], bF[2][4][2];

        #pragma unroll 1
        for (int s = 0; s < 3; ++s) {
            load_ks(smemB, aLane, bLane, mb, h, s, 0, aF[0], bF[0]);
            #pragma unroll 2
            for (int j = 0; j < 18; ++j) {
                const int cur = j & 1, nxt = cur ^ 1;
                if (j < 17)
                    load_ks(smemB, aLane, bLane, mb, h, s, j + 1, aF[nxt], bF[nxt]);
                #pragma unroll
                for (int mf = 0; mf < 2; ++mf)
                    #pragma unroll
                    for (int nf = 0; nf < 4; ++nf)
                        mma16816(acc[mf][nf], aF[cur][mf],
                                 bF[cur][nf][0], bF[cur][nf][1]);
            }
            if (s == 0) {
                __syncthreads();             // all kh=0 reads of slot (h-1)%3 done
                if (i < RPC - 1) {
                    const int hp = h + 2;    // prefetch into freed slot (h-1)%3
                    for (int q = tid; q < 1560; q += 256) {
                        const int kd = q / 520, r = q % 520;
                        const int dp = d + kd - 1;
                        if (dp < 0 || dp >= 64) continue;   // slot stays zero
                        const int wp = r >> 2, part = r & 3;
                        const uint32_t dst = smemB
                            + (kd * 3 + (hp % 3)) * TILE_B
                            + wp * SROW_BYTES + part * 16;
                        const int hps = (hp < 128) ? hp : 127;
                        const char* src = (const char*)
                            (g_sign + (size_t)(dp * 128 + hps) * 4160)
                            + wp * 64 + part * 16;
                        cp16(dst, src, (hp < 128) ? 16u : 0u);
                    }
                    CP_COMMIT();
                }
            }
        }

        // ---- epilogue: direct sector-coalesced stores with bias ----
        float* op = out + (size_t)d * 16384 + (size_t)h * 128;
        #pragma unroll
        for (int mf = 0; mf < 2; ++mf) {
            #pragma unroll
            for (int nf = 0; nf < 4; ++nf) {
                const int o0 = nb + nf * 8 + 2 * tt;
                const int w0 = mb + mf * 16 + g;
                op[(size_t)o0 * 1048576 + w0]           = acc[mf][nf][0] + bReg[nf][0];
                op[(size_t)(o0 + 1) * 1048576 + w0]     = acc[mf][nf][1] + bReg[nf][1];
                op[(size_t)o0 * 1048576 + w0 + 8]       = acc[mf][nf][2] + bReg[nf][0];
                op[(size_t)(o0 + 1) * 1048576 + w0 + 8] = acc[mf][nf][3] + bReg[nf][1];
            }
        }

        if (i < RPC - 1) CP_WAIT0();
        __syncthreads();                      // h+2 tiles visible to all
    }
}

extern "C" void kernel_launch(void* const* d_in, const int* in_sizes, int n_in,
                              void* d_out, int out_size) {
    const float* x  = (const float*)d_in[0];
    const float* Wf = (const float*)d_in[1];
    const float* b  = (const float*)d_in[2];
    float* out = (float*)d_out;

    static bool attr_done = false;
    if (!attr_done) {
        cudaFuncSetAttribute(conv_p,
                             cudaFuncAttributeMaxDynamicSharedMemorySize, SMEM_TOTAL);
        attr_done = true;
    }

    sign_kernel<<<DD * HH, 256>>>(x);
    wprep_kernel<<<(64 * 864 + 255) / 256, 256>>>(Wf);
    conv_p<<<DD * 16, 256, SMEM_TOTAL>>>(b, out);
}